// round 6
// baseline (speedup 1.0000x reference)
#include <cuda_runtime.h>
#include <cstdint>

#define NNODES 50000
#define EMAX   1000000

// ---------------- scratch (__device__ globals; no allocation) ----------------
__device__ float g_xl [(size_t)NNODES * 96];   // x  @ w1_l.T
__device__ float g_h1 [(size_t)NNODES * 96];   // layer-1: self term, then final
__device__ float g_h1l[(size_t)NNODES * 48];   // h1 @ w2_l.T
__device__ float g_wt1[96 * 192];              // transposed combined [k][o] (w1_l | w1_r)
__device__ float g_wt2[96 * 96];               // transposed combined [k][o] (w2_l | w2_r)
__device__ int   g_deg[NNODES];
__device__ int   g_off[NNODES + 1];
__device__ int   g_cur[NNODES];
__device__ int   g_adj[EMAX];                  // CSR-by-dst: src ids

// ---------------- f32x2 packed FMA (sm_103a; PTX-only) ----------------
__device__ __forceinline__ unsigned long long pack2(float x, float y) {
    unsigned long long r;
    asm("mov.b64 %0, {%1, %2};" : "=l"(r) : "f"(x), "f"(y));
    return r;
}
__device__ __forceinline__ unsigned long long ffma2(unsigned long long a,
                                                    unsigned long long b,
                                                    unsigned long long c) {
    unsigned long long d;
    asm("fma.rn.f32x2 %0, %1, %2, %3;" : "=l"(d) : "l"(a), "l"(b), "l"(c));
    return d;
}

// ---------------- weight pre-transpose ----------------
__global__ void prep_weights(const float* __restrict__ w1l, const float* __restrict__ w1r,
                             const float* __restrict__ w2l, const float* __restrict__ w2r) {
    int tid = blockIdx.x * blockDim.x + threadIdx.x;
    int stride = blockDim.x * gridDim.x;
    for (int i = tid; i < 96 * 96; i += stride) {
        int o = i / 96, k = i % 96;
        g_wt1[k * 192 + o]      = w1l[i];
        g_wt1[k * 192 + 96 + o] = w1r[i];
    }
    for (int i = tid; i < 48 * 96; i += stride) {
        int o = i / 96, k = i % 96;
        g_wt2[k * 96 + o]      = w2l[i];
        g_wt2[k * 96 + 48 + o] = w2r[i];
    }
}

// ---------------- CSR build ----------------
__global__ void hist_k(const int* __restrict__ ei, int E) {
    int i = blockIdx.x * blockDim.x + threadIdx.x;
    if (i < E) atomicAdd(&g_deg[ei[E + i]], 1);
}

__global__ void scan_k(int N) {   // single block, 1024 threads
    __shared__ int part[1024];
    int tid = threadIdx.x;
    int chunk = (N + 1023) >> 10;
    int b = tid * chunk, e = b + chunk;
    if (b > N) b = N;
    if (e > N) e = N;
    int s = 0;
    for (int i = b; i < e; i++) s += g_deg[i];
    part[tid] = s;
    __syncthreads();
    for (int d = 1; d < 1024; d <<= 1) {
        int v = (tid >= d) ? part[tid - d] : 0;
        __syncthreads();
        part[tid] += v;
        __syncthreads();
    }
    int base = (tid == 0) ? 0 : part[tid - 1];
    for (int i = b; i < e; i++) {
        g_off[i] = base;
        g_cur[i] = base;
        base += g_deg[i];
    }
    if (tid == 1023) g_off[N] = part[1023];
}

__global__ void fill_k(const int* __restrict__ ei, int E) {
    int i = blockIdx.x * blockDim.x + threadIdx.x;
    if (i < E) {
        int s = ei[i], d = ei[E + i];
        int p = atomicAdd(&g_cur[d], 1);
        g_adj[p] = s;
    }
}

// ---------------- fused dual-output GEMM with FFMA2 ----------------
// NP = f32x2 pairs per lane (192->3, 96->1); OUT=96 adds one scalar column/lane.
// Pair cols: lane*2*NP + 2j (contiguous -> LDS.64 for W, float2 stores).
// Scalar col (OUT=96): 64*NP + lane.
template<int OUT>
__global__ void gemm_k(const float* __restrict__ xin, const float* __restrict__ wt,
                       const float* __restrict__ bias,
                       float* __restrict__ outa, float* __restrict__ outb, int nrows) {
    constexpr int  NP   = OUT / 64;
    constexpr bool SC   = (OUT % 64) != 0;
    constexpr int  HALF = OUT / 2;
    extern __shared__ float sm[];
    float* wTs = sm;              // 96*OUT
    float* xs  = sm + 96 * OUT;   // 64*96 row-major
    const int tid = threadIdx.x;

    for (int f = tid; f < 96 * OUT / 4; f += 256)
        ((float4*)wTs)[f] = ((const float4*)wt)[f];

    const int row0 = blockIdx.x * 64;
    for (int f = tid; f < 64 * 24; f += 256) {
        int r = f / 24, c = f % 24;
        float4 v = make_float4(0.f, 0.f, 0.f, 0.f);
        if (row0 + r < nrows) v = ((const float4*)xin)[(size_t)(row0 + r) * 24 + c];
        ((float4*)xs)[f] = v;
    }
    __syncthreads();

    const int warp = tid >> 5, lane = tid & 31;
    const int rb = warp * 8;
    const int pc = lane * 2 * NP;

    unsigned long long acc2[8][NP];
    float accs[8];
#pragma unroll
    for (int m = 0; m < 8; m++) {
#pragma unroll
        for (int j = 0; j < NP; j++) acc2[m][j] = 0ull;
        accs[m] = 0.f;
    }

    const float* wp  = wTs + pc;
    const float* wsp = wTs + 64 * NP + lane;

#pragma unroll 2
    for (int k = 0; k < 96; k++) {
        unsigned long long w2[NP];
#pragma unroll
        for (int j = 0; j < NP; j++)
            w2[j] = *(const unsigned long long*)(wp + k * OUT + 2 * j);
        float ws = SC ? wsp[k * OUT] : 0.f;
#pragma unroll
        for (int m = 0; m < 8; m++) {
            float x = xs[(rb + m) * 96 + k];
            unsigned long long x2 = pack2(x, x);
#pragma unroll
            for (int j = 0; j < NP; j++) acc2[m][j] = ffma2(x2, w2[j], acc2[m][j]);
            if (SC) accs[m] = fmaf(x, ws, accs[m]);
        }
    }

#pragma unroll
    for (int m = 0; m < 8; m++) {
        int r = row0 + rb + m;
        if (r >= nrows) break;
#pragma unroll
        for (int j = 0; j < NP; j++) {
            int c = pc + 2 * j;                   // pairs never straddle HALF
            float2 v = *(float2*)&acc2[m][j];
            if (c < HALF) {
                *(float2*)(outa + (size_t)r * HALF + c) = v;
            } else {
                int cb = c - HALF;
                float2 bv = *(const float2*)(bias + cb);
                v.x += bv.x; v.y += bv.y;
                *(float2*)(outb + (size_t)r * HALF + cb) = v;
            }
        }
        if (SC) {
            int cb = 64 * NP + lane - HALF;       // always in outb
            outb[(size_t)r * HALF + cb] = accs[m] + __ldg(&bias[cb]);
        }
    }
}

// ---------------- fused CSR mean-aggregate ----------------
// layer 1: h1 = relu(mean_j xl[j] + h1_self)   (warp per node, 24 lanes x float4)
__global__ void agg1_k(int N) {
    int w    = (blockIdx.x * blockDim.x + threadIdx.x) >> 5;
    int lane = threadIdx.x & 31;
    if (w >= N || lane >= 24) return;
    int b = g_off[w], e = g_off[w + 1];
    const float4* f4 = (const float4*)g_xl;
    float4 acc = make_float4(0.f, 0.f, 0.f, 0.f);
    int j = b;
    for (; j + 1 < e; j += 2) {
        int s0 = __ldg(&g_adj[j]), s1 = __ldg(&g_adj[j + 1]);
        float4 v0 = __ldg(f4 + (size_t)s0 * 24 + lane);
        float4 v1 = __ldg(f4 + (size_t)s1 * 24 + lane);
        acc.x += v0.x + v1.x; acc.y += v0.y + v1.y;
        acc.z += v0.z + v1.z; acc.w += v0.w + v1.w;
    }
    if (j < e) {
        int s0 = __ldg(&g_adj[j]);
        float4 v0 = __ldg(f4 + (size_t)s0 * 24 + lane);
        acc.x += v0.x; acc.y += v0.y; acc.z += v0.z; acc.w += v0.w;
    }
    float inv = 1.0f / fmaxf((float)(e - b), 1.0f);
    float4* h4 = (float4*)g_h1;
    float4 h = h4[(size_t)w * 24 + lane];
    float4 r;
    r.x = fmaxf(fmaf(acc.x, inv, h.x), 0.f);
    r.y = fmaxf(fmaf(acc.y, inv, h.y), 0.f);
    r.z = fmaxf(fmaf(acc.z, inv, h.z), 0.f);
    r.w = fmaxf(fmaf(acc.w, inv, h.w), 0.f);
    h4[(size_t)w * 24 + lane] = r;
}

// layer 2: out += mean_j h1l[j]   (2 nodes per warp, 12 float4 chunks each)
__global__ void agg2_k(float* __restrict__ out, int N) {
    int w    = (blockIdx.x * blockDim.x + threadIdx.x) >> 5;
    int lane = threadIdx.x & 31;
    if (lane >= 24) return;
    int node = w * 2 + (lane / 12);
    int ch   = lane % 12;
    if (node >= N) return;
    int b = g_off[node], e = g_off[node + 1];
    const float4* f4 = (const float4*)g_h1l;
    float4 acc = make_float4(0.f, 0.f, 0.f, 0.f);
    int j = b;
    for (; j + 1 < e; j += 2) {
        int s0 = __ldg(&g_adj[j]), s1 = __ldg(&g_adj[j + 1]);
        float4 v0 = __ldg(f4 + (size_t)s0 * 12 + ch);
        float4 v1 = __ldg(f4 + (size_t)s1 * 12 + ch);
        acc.x += v0.x + v1.x; acc.y += v0.y + v1.y;
        acc.z += v0.z + v1.z; acc.w += v0.w + v1.w;
    }
    if (j < e) {
        int s0 = __ldg(&g_adj[j]);
        float4 v0 = __ldg(f4 + (size_t)s0 * 12 + ch);
        acc.x += v0.x; acc.y += v0.y; acc.z += v0.z; acc.w += v0.w;
    }
    float inv = 1.0f / fmaxf((float)(e - b), 1.0f);
    float4* o4 = (float4*)out;
    float4 o = o4[(size_t)node * 12 + ch];
    o.x = fmaf(acc.x, inv, o.x);
    o.y = fmaf(acc.y, inv, o.y);
    o.z = fmaf(acc.z, inv, o.z);
    o.w = fmaf(acc.w, inv, o.w);
    o4[(size_t)node * 12 + ch] = o;
}

// ---------------- launch ----------------
extern "C" void kernel_launch(void* const* d_in, const int* in_sizes, int n_in,
                              void* d_out, int out_size) {
    const float* x   = (const float*)d_in[0];
    const int*   ei  = (const int*)d_in[1];     // int32 (JAX x64 disabled)
    const float* w1l = (const float*)d_in[2];
    const float* b1  = (const float*)d_in[3];
    const float* w1r = (const float*)d_in[4];
    const float* w2l = (const float*)d_in[5];
    const float* b2  = (const float*)d_in[6];
    const float* w2r = (const float*)d_in[7];
    float*       out = (float*)d_out;

    const int N = in_sizes[0] / 96;     // 50000
    const int E = in_sizes[1] / 2;      // 800000

    void *p_xl, *p_h1, *p_h1l, *p_wt1, *p_wt2, *p_deg;
    cudaGetSymbolAddress(&p_xl,  g_xl);
    cudaGetSymbolAddress(&p_h1,  g_h1);
    cudaGetSymbolAddress(&p_h1l, g_h1l);
    cudaGetSymbolAddress(&p_wt1, g_wt1);
    cudaGetSymbolAddress(&p_wt2, g_wt2);
    cudaGetSymbolAddress(&p_deg, g_deg);

    static bool attr_done = false;
    if (!attr_done) {
        cudaFuncSetAttribute(gemm_k<192>,
                             cudaFuncAttributeMaxDynamicSharedMemorySize,
                             (96 * 192 + 64 * 96) * 4);
        cudaFuncSetAttribute(gemm_k<96>,
                             cudaFuncAttributeMaxDynamicSharedMemorySize,
                             (96 * 96 + 64 * 96) * 4);
        attr_done = true;
    }

    // CSR build (shared by both layers)
    cudaMemsetAsync(p_deg, 0, (size_t)N * sizeof(int), 0);
    prep_weights<<<64, 256>>>(w1l, w1r, w2l, w2r);
    const int eb = (E + 255) / 256;
    hist_k<<<eb, 256>>>(ei, E);
    scan_k<<<1, 1024>>>(N);
    fill_k<<<eb, 256>>>(ei, E);

    const int gemm_blocks = (N + 63) / 64;

    // layer 1: xl = x @ w1_l.T ; h1 = x @ w1_r.T + b1
    gemm_k<192><<<gemm_blocks, 256, (96 * 192 + 64 * 96) * 4>>>(
        x, (const float*)p_wt1, b1, (float*)p_xl, (float*)p_h1, N);

    // h1 = relu(mean gather(xl) + h1)
    agg1_k<<<(N * 32 + 255) / 256, 256>>>(N);

    // layer 2: h1l = h1 @ w2_l.T ; out = h1 @ w2_r.T + b2
    gemm_k<96><<<gemm_blocks, 256, (96 * 96 + 64 * 96) * 4>>>(
        (const float*)p_h1, (const float*)p_wt2, b2, (float*)p_h1l, out, N);

    // out += mean gather(h1l)
    agg2_k<<<(((N + 1) / 2) * 32 + 255) / 256, 256>>>(out, N);
}